// round 1
// baseline (speedup 1.0000x reference)
#include <cuda_runtime.h>

#define N_NODES 100000
#define E_INTRA 1000000
#define E_INTER 500000
#define E_TOT   (E_INTRA + E_INTER)

// ---------------- scratch (device globals: no allocs allowed) ----------------
__device__ float    g_h[(size_t)N_NODES * 1024];   // [n][pass(4)][head(4)][c(64)]  ~410MB
__device__ float    g_as[N_NODES * 16];            // [n][pass][head]
__device__ float    g_ad[N_NODES * 16];
__device__ unsigned g_menc[N_NODES * 16];          // ordered-uint encoded segment max
__device__ float    g_den[N_NODES * 16];           // softmax denominators
__device__ float    g_ebuf[(size_t)E_TOT * 4];     // per-edge logits, then p values
__device__ float    g_fold[64 * 32];               // folded attention weights [f][sd*16+p*4+h]

// ordered-uint encoding for float atomicMax (monotone map)
__device__ __forceinline__ unsigned fenc(float f) {
    unsigned u = __float_as_uint(f);
    return (u & 0x80000000u) ? ~u : (u | 0x80000000u);
}
__device__ __forceinline__ float fdec(unsigned e) {
    return (e & 0x80000000u) ? __uint_as_float(e ^ 0x80000000u)
                             : __uint_as_float(~e);
}

// ---------------- fold: w_fold[f][o] = sum_c W_p[f][h*64+c] * att_{sd,p}[h][c] ----
__global__ void fold_k(const float* __restrict__ Wi, const float* __restrict__ asi,
                       const float* __restrict__ adi, const float* __restrict__ Ww,
                       const float* __restrict__ asw, const float* __restrict__ adw) {
    int idx = blockIdx.x * blockDim.x + threadIdx.x;
    if (idx >= 64 * 32) return;
    int f = idx >> 5, o = idx & 31;
    int sd = o >> 4, p = (o >> 2) & 3, h = o & 3;
    const float* W = (p < 3) ? (Wi + p * 64 * 256) : Ww;
    const float* att;
    if (p < 3) att = (sd ? adi : asi) + p * 4 * 64 + h * 64;
    else       att = (sd ? adw : asw) + h * 64;
    const float* wr = W + f * 256 + h * 64;
    float s = 0.f;
    #pragma unroll 16
    for (int c = 0; c < 64; c++) s += wr[c] * att[c];
    g_fold[f * 32 + o] = s;
}

// ---------------- a_s / a_d = x @ fold  (thread per node) ----------------
__global__ __launch_bounds__(256) void asd_k(const float* __restrict__ x) {
    __shared__ float sf[64 * 32];
    for (int i = threadIdx.x; i < 2048; i += 256) sf[i] = g_fold[i];
    __syncthreads();
    int n = blockIdx.x * blockDim.x + threadIdx.x;
    if (n >= N_NODES) return;
    float acc[32];
    #pragma unroll
    for (int o = 0; o < 32; o++) acc[o] = 0.f;
    const float4* xr = (const float4*)(x + (size_t)n * 64);
    #pragma unroll
    for (int f4 = 0; f4 < 16; f4++) {
        float4 xv = __ldg(xr + f4);
        int f = f4 * 4;
        #pragma unroll
        for (int o = 0; o < 32; o++) {
            acc[o] += xv.x * sf[(f + 0) * 32 + o] + xv.y * sf[(f + 1) * 32 + o]
                    + xv.z * sf[(f + 2) * 32 + o] + xv.w * sf[(f + 3) * 32 + o];
        }
    }
    float4* as4 = (float4*)(g_as + n * 16);
    float4* ad4 = (float4*)(g_ad + n * 16);
    #pragma unroll
    for (int q = 0; q < 4; q++) {
        as4[q] = make_float4(acc[q * 4 + 0], acc[q * 4 + 1], acc[q * 4 + 2], acc[q * 4 + 3]);
        ad4[q] = make_float4(acc[16 + q * 4 + 0], acc[16 + q * 4 + 1], acc[16 + q * 4 + 2], acc[16 + q * 4 + 3]);
    }
}

// ---------------- h = x @ W_p : 64x64 tile, K=64 in one smem load ----------------
__global__ __launch_bounds__(256) void gemm_k(const float* __restrict__ x,
                                              const float* __restrict__ Wi,
                                              const float* __restrict__ Ww) {
    __shared__ float xsT[64 * 64];  // [k][row]
    __shared__ float ws[64 * 64];   // [k][col]
    int p = blockIdx.z;
    const float* W = (p < 3) ? (Wi + p * 64 * 256) : Ww;
    int row0 = blockIdx.x * 64;
    int col0 = blockIdx.y * 64;
    int tid = threadIdx.x;
    #pragma unroll
    for (int i = 0; i < 4; i++) {
        int idx = tid + i * 256;        // float4 slot 0..1023
        int r = idx >> 4, kq = idx & 15;
        float4 v = make_float4(0.f, 0.f, 0.f, 0.f);
        int row = row0 + r;
        if (row < N_NODES) v = *(const float4*)(x + (size_t)row * 64 + kq * 4);
        xsT[(kq * 4 + 0) * 64 + r] = v.x;
        xsT[(kq * 4 + 1) * 64 + r] = v.y;
        xsT[(kq * 4 + 2) * 64 + r] = v.z;
        xsT[(kq * 4 + 3) * 64 + r] = v.w;
        int k = idx >> 4, cq = idx & 15;
        *(float4*)(ws + k * 64 + cq * 4) = *(const float4*)(W + k * 256 + col0 + cq * 4);
    }
    __syncthreads();
    int tx = tid & 15, ty = tid >> 4;
    float acc[4][4] = {};
    #pragma unroll 8
    for (int k = 0; k < 64; k++) {
        float4 a = *(const float4*)(xsT + k * 64 + ty * 4);
        float4 b = *(const float4*)(ws + k * 64 + tx * 4);
        acc[0][0] += a.x * b.x; acc[0][1] += a.x * b.y; acc[0][2] += a.x * b.z; acc[0][3] += a.x * b.w;
        acc[1][0] += a.y * b.x; acc[1][1] += a.y * b.y; acc[1][2] += a.y * b.z; acc[1][3] += a.y * b.w;
        acc[2][0] += a.z * b.x; acc[2][1] += a.z * b.y; acc[2][2] += a.z * b.z; acc[2][3] += a.z * b.w;
        acc[3][0] += a.w * b.x; acc[3][1] += a.w * b.y; acc[3][2] += a.w * b.z; acc[3][3] += a.w * b.w;
    }
    #pragma unroll
    for (int i = 0; i < 4; i++) {
        int row = row0 + ty * 4 + i;
        if (row < N_NODES) {
            *(float4*)(g_h + (size_t)row * 1024 + p * 256 + col0 + tx * 4) =
                make_float4(acc[i][0], acc[i][1], acc[i][2], acc[i][3]);
        }
    }
}

// ---------------- init kernels ----------------
__global__ void init_md_k() {
    int i = blockIdx.x * blockDim.x + threadIdx.x;
    if (i < N_NODES * 16) { g_menc[i] = 0u; g_den[i] = 0.f; }
}
__global__ void init_out_k(float* __restrict__ out, const float* __restrict__ bi,
                           const float* __restrict__ bw) {
    int i = blockIdx.x * blockDim.x + threadIdx.x;
    if (i < N_NODES * 64) {
        int c = i & 63;
        out[i] = bi[c] + bi[64 + c] + bi[128 + c] + bw[c];
    }
}

// ---------------- edge pass 1: logits + segment max ----------------
__global__ void edge_max_k(const int* __restrict__ src, const int* __restrict__ dst,
                           const int* __restrict__ mod, int E, int eoff) {
    int e = blockIdx.x * blockDim.x + threadIdx.x;
    if (e >= E) return;
    int p = mod ? __ldg(mod + e) : 3;
    int s = __ldg(src + e), d = __ldg(dst + e);
    float4 as = *(const float4*)(g_as + s * 16 + p * 4);
    float4 ad = *(const float4*)(g_ad + d * 16 + p * 4);
    float v0 = as.x + ad.x; v0 = v0 > 0.f ? v0 : 0.2f * v0;
    float v1 = as.y + ad.y; v1 = v1 > 0.f ? v1 : 0.2f * v1;
    float v2 = as.z + ad.z; v2 = v2 > 0.f ? v2 : 0.2f * v2;
    float v3 = as.w + ad.w; v3 = v3 > 0.f ? v3 : 0.2f * v3;
    *(float4*)(g_ebuf + (size_t)(e + eoff) * 4) = make_float4(v0, v1, v2, v3);
    unsigned* mp = g_menc + d * 16 + p * 4;
    atomicMax(mp + 0, fenc(v0));
    atomicMax(mp + 1, fenc(v1));
    atomicMax(mp + 2, fenc(v2));
    atomicMax(mp + 3, fenc(v3));
}

// ---------------- edge pass 2: p = exp(e - m), segment sum ----------------
__global__ void edge_psum_k(const int* __restrict__ dst, const int* __restrict__ mod,
                            int E, int eoff) {
    int e = blockIdx.x * blockDim.x + threadIdx.x;
    if (e >= E) return;
    int p = mod ? __ldg(mod + e) : 3;
    int d = __ldg(dst + e);
    float4 v = *(const float4*)(g_ebuf + (size_t)(e + eoff) * 4);
    uint4 mu = *(const uint4*)(g_menc + d * 16 + p * 4);
    float p0 = expf(v.x - fdec(mu.x));
    float p1 = expf(v.y - fdec(mu.y));
    float p2 = expf(v.z - fdec(mu.z));
    float p3 = expf(v.w - fdec(mu.w));
    *(float4*)(g_ebuf + (size_t)(e + eoff) * 4) = make_float4(p0, p1, p2, p3);
    float* dp = g_den + d * 16 + p * 4;
    atomicAdd(dp + 0, p0);
    atomicAdd(dp + 1, p1);
    atomicAdd(dp + 2, p2);
    atomicAdd(dp + 3, p3);
}

// ---------------- edge pass 3: aggregate (warp per edge, head-avg fused) ----------
__global__ __launch_bounds__(256) void agg_k(const int* __restrict__ src,
                                             const int* __restrict__ dst,
                                             const int* __restrict__ mod,
                                             int E, int eoff, float* __restrict__ out) {
    int gw = (blockIdx.x * blockDim.x + threadIdx.x) >> 5;
    int lane = threadIdx.x & 31;
    if (gw >= E) return;
    int e = gw;
    int p = mod ? __ldg(mod + e) : 3;
    int s = __ldg(src + e), d = __ldg(dst + e);
    float4 pv = *(const float4*)(g_ebuf + (size_t)(e + eoff) * 4);
    float4 dn = *(const float4*)(g_den + d * 16 + p * 4);
    float a0 = pv.x / fmaxf(dn.x, 1e-16f) * 0.25f;
    float a1 = pv.y / fmaxf(dn.y, 1e-16f) * 0.25f;
    float a2 = pv.z / fmaxf(dn.z, 1e-16f) * 0.25f;
    float a3 = pv.w / fmaxf(dn.w, 1e-16f) * 0.25f;
    const float* hr = g_h + (size_t)s * 1024 + p * 256;
    float acc0 = a0 * hr[lane]       + a1 * hr[64 + lane]
               + a2 * hr[128 + lane] + a3 * hr[192 + lane];
    float acc1 = a0 * hr[32 + lane]  + a1 * hr[96 + lane]
               + a2 * hr[160 + lane] + a3 * hr[224 + lane];
    atomicAdd(out + (size_t)d * 64 + lane, acc0);
    atomicAdd(out + (size_t)d * 64 + 32 + lane, acc1);
}

// ---------------- launch ----------------
extern "C" void kernel_launch(void* const* d_in, const int* in_sizes, int n_in,
                              void* d_out, int out_size) {
    const float* x        = (const float*)d_in[0];
    const int*   modality = (const int*)d_in[1];
    const int*   isrc     = (const int*)d_in[2];
    const int*   idst     = (const int*)d_in[3];
    const int*   wsrc     = (const int*)d_in[4];
    const int*   wdst     = (const int*)d_in[5];
    const float* W_intra  = (const float*)d_in[6];
    const float* as_i     = (const float*)d_in[7];
    const float* ad_i     = (const float*)d_in[8];
    const float* b_i      = (const float*)d_in[9];
    const float* W_inter  = (const float*)d_in[10];
    const float* as_w     = (const float*)d_in[11];
    const float* ad_w     = (const float*)d_in[12];
    const float* b_w      = (const float*)d_in[13];
    float* out = (float*)d_out;

    fold_k<<<8, 256>>>(W_intra, as_i, ad_i, W_inter, as_w, ad_w);
    asd_k<<<(N_NODES + 255) / 256, 256>>>(x);
    gemm_k<<<dim3((N_NODES + 63) / 64, 4, 4), 256>>>(x, W_intra, W_inter);
    init_md_k<<<(N_NODES * 16 + 255) / 256, 256>>>();
    init_out_k<<<(N_NODES * 64 + 255) / 256, 256>>>(out, b_i, b_w);

    edge_max_k<<<(E_INTRA + 255) / 256, 256>>>(isrc, idst, modality, E_INTRA, 0);
    edge_max_k<<<(E_INTER + 255) / 256, 256>>>(wsrc, wdst, nullptr, E_INTER, E_INTRA);

    edge_psum_k<<<(E_INTRA + 255) / 256, 256>>>(idst, modality, E_INTRA, 0);
    edge_psum_k<<<(E_INTER + 255) / 256, 256>>>(wdst, nullptr, E_INTER, E_INTRA);

    agg_k<<<((size_t)E_INTRA * 32 + 255) / 256, 256>>>(isrc, idst, modality, E_INTRA, 0, out);
    agg_k<<<((size_t)E_INTER * 32 + 255) / 256, 256>>>(wsrc, wdst, nullptr, E_INTER, E_INTRA, out);
}

// round 2
// speedup vs baseline: 1.3592x; 1.3592x over previous
#include <cuda_runtime.h>

#define N_NODES 100000
#define E_INTRA 1000000
#define E_INTER 500000
#define E_TOT   (E_INTRA + E_INTER)
#define SHIFT   10.0f

// ---------------- scratch (device globals: no allocs allowed) ----------------
__device__ float    g_h[(size_t)4 * N_NODES * 256]; // [pass][n][head*64+c]  ~410MB
__device__ float    g_as[N_NODES * 16];             // [n][pass][head]
__device__ float    g_ad[N_NODES * 16];
__device__ float    g_den[N_NODES * 16];            // softmax denominators
__device__ float    g_ebuf[(size_t)E_TOT * 4];      // per-edge p values (bin order for intra)
__device__ float    g_fold[64 * 32];                // folded attention weights
__device__ int      g_bsrc[E_INTRA];                // binned intra edges
__device__ int      g_bdst[E_INTRA];
__device__ int      g_cnt[4];
__device__ int      g_base[4];
__device__ int      g_cur[4];

// ---------------- f32x2 packed math helpers ----------------
__device__ __forceinline__ unsigned long long pk2(float x) {
    unsigned long long r;
    asm("mov.b64 %0, {%1, %1};" : "=l"(r) : "f"(x));
    return r;
}
__device__ __forceinline__ void fma2(unsigned long long& acc, unsigned long long a,
                                     unsigned long long b) {
    asm("fma.rn.f32x2 %0, %1, %2, %0;" : "+l"(acc) : "l"(a), "l"(b));
}
__device__ __forceinline__ float2 upk(unsigned long long v) {
    float2 f;
    asm("mov.b64 {%0, %1}, %2;" : "=f"(f.x), "=f"(f.y) : "l"(v));
    return f;
}

// ---------------- fold: w_fold[f][o] = sum_c W_p[f][h*64+c] * att[h][c] ----
__global__ void fold_k(const float* __restrict__ Wi, const float* __restrict__ asi,
                       const float* __restrict__ adi, const float* __restrict__ Ww,
                       const float* __restrict__ asw, const float* __restrict__ adw) {
    int idx = blockIdx.x * blockDim.x + threadIdx.x;
    if (idx >= 64 * 32) return;
    int f = idx >> 5, o = idx & 31;
    int sd = o >> 4, p = (o >> 2) & 3, h = o & 3;
    const float* W = (p < 3) ? (Wi + p * 64 * 256) : Ww;
    const float* att;
    if (p < 3) att = (sd ? adi : asi) + p * 4 * 64 + h * 64;
    else       att = (sd ? adw : asw) + h * 64;
    const float* wr = W + f * 256 + h * 64;
    float s = 0.f;
    #pragma unroll 16
    for (int c = 0; c < 64; c++) s += wr[c] * att[c];
    g_fold[f * 32 + o] = s;
}

// ---------------- a_s / a_d = x @ fold  (thread per node) ----------------
__global__ __launch_bounds__(256) void asd_k(const float* __restrict__ x) {
    __shared__ float sf[64 * 32];
    for (int i = threadIdx.x; i < 2048; i += 256) sf[i] = g_fold[i];
    __syncthreads();
    int n = blockIdx.x * blockDim.x + threadIdx.x;
    if (n >= N_NODES) return;
    float acc[32];
    #pragma unroll
    for (int o = 0; o < 32; o++) acc[o] = 0.f;
    const float4* xr = (const float4*)(x + (size_t)n * 64);
    #pragma unroll
    for (int f4 = 0; f4 < 16; f4++) {
        float4 xv = __ldg(xr + f4);
        int f = f4 * 4;
        #pragma unroll
        for (int o = 0; o < 32; o++) {
            acc[o] += xv.x * sf[(f + 0) * 32 + o] + xv.y * sf[(f + 1) * 32 + o]
                    + xv.z * sf[(f + 2) * 32 + o] + xv.w * sf[(f + 3) * 32 + o];
        }
    }
    float4* as4 = (float4*)(g_as + n * 16);
    float4* ad4 = (float4*)(g_ad + n * 16);
    #pragma unroll
    for (int q = 0; q < 4; q++) {
        as4[q] = make_float4(acc[q * 4 + 0], acc[q * 4 + 1], acc[q * 4 + 2], acc[q * 4 + 3]);
        ad4[q] = make_float4(acc[16 + q * 4 + 0], acc[16 + q * 4 + 1], acc[16 + q * 4 + 2], acc[16 + q * 4 + 3]);
    }
}

// ---------------- h = x @ W_p : 128x128 tile, K=64, f32x2 FMA ----------------
#define XS_PITCH 68
__global__ __launch_bounds__(256, 2) void gemm2_k(const float* __restrict__ x,
                                                  const float* __restrict__ Wi,
                                                  const float* __restrict__ Ww) {
    extern __shared__ float smem[];
    float* xs = smem;                 // [128][XS_PITCH]
    float* ws = smem + 128 * XS_PITCH; // [64][128]
    int p = blockIdx.z;
    const float* W = (p < 3) ? (Wi + p * 64 * 256) : Ww;
    int row0 = blockIdx.x * 128;
    int col0 = blockIdx.y * 128;
    int tid = threadIdx.x;

    // load x tile [128 rows][64 k], row-major with pad
    #pragma unroll
    for (int i = 0; i < 8; i++) {
        int idx = tid + i * 256;          // 0..2047 float4 slots
        int r = idx >> 4, kq = idx & 15;
        float4 v = make_float4(0.f, 0.f, 0.f, 0.f);
        int row = row0 + r;
        if (row < N_NODES) v = *(const float4*)(x + (size_t)row * 64 + kq * 4);
        *(float4*)(xs + r * XS_PITCH + kq * 4) = v;
    }
    // load W tile [64 k][128 cols]
    #pragma unroll
    for (int i = 0; i < 8; i++) {
        int idx = tid + i * 256;          // 0..2047 float4 slots
        int k = idx >> 5, cq = idx & 31;
        *(float4*)(ws + k * 128 + cq * 4) = *(const float4*)(W + k * 256 + col0 + cq * 4);
    }
    __syncthreads();

    int tx = tid & 15, ty = tid >> 4;     // tx: 8-col group, ty: 8-row group
    unsigned long long acc[8][4];
    #pragma unroll
    for (int i = 0; i < 8; i++)
        #pragma unroll
        for (int j = 0; j < 4; j++) acc[i][j] = 0ull;

    const float* xbase = xs + ty * 8 * XS_PITCH;
    #pragma unroll 8
    for (int k = 0; k < 64; k++) {
        ulonglong2 B0 = *(const ulonglong2*)(ws + k * 128 + tx * 8);
        ulonglong2 B1 = *(const ulonglong2*)(ws + k * 128 + tx * 8 + 4);
        #pragma unroll
        for (int i = 0; i < 8; i++) {
            unsigned long long aa = pk2(xbase[i * XS_PITCH + k]);
            fma2(acc[i][0], aa, B0.x);
            fma2(acc[i][1], aa, B0.y);
            fma2(acc[i][2], aa, B1.x);
            fma2(acc[i][3], aa, B1.y);
        }
    }

    #pragma unroll
    for (int i = 0; i < 8; i++) {
        int row = row0 + ty * 8 + i;
        if (row < N_NODES) {
            float* op = g_h + ((size_t)p * N_NODES + row) * 256 + col0 + tx * 8;
            float2 f0 = upk(acc[i][0]), f1 = upk(acc[i][1]);
            float2 f2 = upk(acc[i][2]), f3 = upk(acc[i][3]);
            *(float4*)(op)     = make_float4(f0.x, f0.y, f1.x, f1.y);
            *(float4*)(op + 4) = make_float4(f2.x, f2.y, f3.x, f3.y);
        }
    }
}

// ---------------- init kernels ----------------
__global__ void zero_k() {
    int i = blockIdx.x * blockDim.x + threadIdx.x;
    if (i < N_NODES * 16) g_den[i] = 0.f;
    if (i < 4) g_cnt[i] = 0;
}
__global__ void init_out_k(float* __restrict__ out, const float* __restrict__ bi,
                           const float* __restrict__ bw) {
    int i = blockIdx.x * blockDim.x + threadIdx.x;
    if (i < N_NODES * 64) {
        int c = i & 63;
        out[i] = bi[c] + bi[64 + c] + bi[128 + c] + bw[c];
    }
}

// ---------------- modality binning ----------------
__global__ void count_k(const int* __restrict__ mod) {
    __shared__ int sc[3];
    if (threadIdx.x < 3) sc[threadIdx.x] = 0;
    __syncthreads();
    int e = blockIdx.x * blockDim.x + threadIdx.x;
    if (e < E_INTRA) atomicAdd(&sc[__ldg(mod + e)], 1);
    __syncthreads();
    if (threadIdx.x < 3) atomicAdd(&g_cnt[threadIdx.x], sc[threadIdx.x]);
}
__global__ void base_k() {
    g_base[0] = 0;
    g_base[1] = g_cnt[0];
    g_base[2] = g_cnt[0] + g_cnt[1];
    g_base[3] = E_INTRA;
    g_cur[0] = g_base[0]; g_cur[1] = g_base[1]; g_cur[2] = g_base[2];
}
__global__ void scat_k(const int* __restrict__ src, const int* __restrict__ dst,
                       const int* __restrict__ mod) {
    __shared__ int sc[3], sb[3];
    if (threadIdx.x < 3) sc[threadIdx.x] = 0;
    __syncthreads();
    int e = blockIdx.x * blockDim.x + threadIdx.x;
    int m = -1, s = 0, d = 0, lpos = 0;
    if (e < E_INTRA) {
        m = __ldg(mod + e); s = __ldg(src + e); d = __ldg(dst + e);
        lpos = atomicAdd(&sc[m], 1);
    }
    __syncthreads();
    if (threadIdx.x < 3) sb[threadIdx.x] = atomicAdd(&g_cur[threadIdx.x], sc[threadIdx.x]);
    __syncthreads();
    if (e < E_INTRA) {
        int pos = sb[m] + lpos;
        g_bsrc[pos] = s;
        g_bdst[pos] = d;
    }
}

// ---------------- fused edge pass: logit -> exp -> denom ----------------
__global__ void fused_intra_k() {
    int t = blockIdx.x * blockDim.x + threadIdx.x;
    if (t >= E_INTRA) return;
    int m = (t >= g_base[1]) + (t >= g_base[2]);
    int s = g_bsrc[t], d = g_bdst[t];
    float4 as = *(const float4*)(g_as + s * 16 + m * 4);
    float4 ad = *(const float4*)(g_ad + d * 16 + m * 4);
    float v0 = as.x + ad.x; v0 = v0 > 0.f ? v0 : 0.2f * v0;
    float v1 = as.y + ad.y; v1 = v1 > 0.f ? v1 : 0.2f * v1;
    float v2 = as.z + ad.z; v2 = v2 > 0.f ? v2 : 0.2f * v2;
    float v3 = as.w + ad.w; v3 = v3 > 0.f ? v3 : 0.2f * v3;
    float p0 = __expf(v0 - SHIFT), p1 = __expf(v1 - SHIFT);
    float p2 = __expf(v2 - SHIFT), p3 = __expf(v3 - SHIFT);
    *(float4*)(g_ebuf + (size_t)t * 4) = make_float4(p0, p1, p2, p3);
    float* dp = g_den + d * 16 + m * 4;
    atomicAdd(dp + 0, p0);
    atomicAdd(dp + 1, p1);
    atomicAdd(dp + 2, p2);
    atomicAdd(dp + 3, p3);
}
__global__ void fused_inter_k(const int* __restrict__ src, const int* __restrict__ dst) {
    int t = blockIdx.x * blockDim.x + threadIdx.x;
    if (t >= E_INTER) return;
    int s = __ldg(src + t), d = __ldg(dst + t);
    float4 as = *(const float4*)(g_as + s * 16 + 12);
    float4 ad = *(const float4*)(g_ad + d * 16 + 12);
    float v0 = as.x + ad.x; v0 = v0 > 0.f ? v0 : 0.2f * v0;
    float v1 = as.y + ad.y; v1 = v1 > 0.f ? v1 : 0.2f * v1;
    float v2 = as.z + ad.z; v2 = v2 > 0.f ? v2 : 0.2f * v2;
    float v3 = as.w + ad.w; v3 = v3 > 0.f ? v3 : 0.2f * v3;
    float p0 = __expf(v0 - SHIFT), p1 = __expf(v1 - SHIFT);
    float p2 = __expf(v2 - SHIFT), p3 = __expf(v3 - SHIFT);
    *(float4*)(g_ebuf + (size_t)(E_INTRA + t) * 4) = make_float4(p0, p1, p2, p3);
    float* dp = g_den + d * 16 + 12;
    atomicAdd(dp + 0, p0);
    atomicAdd(dp + 1, p1);
    atomicAdd(dp + 2, p2);
    atomicAdd(dp + 3, p3);
}

// ---------------- aggregation: warp per edge, head-avg fused ----------------
__global__ __launch_bounds__(256) void agg_intra_k(float* __restrict__ out) {
    int t = (blockIdx.x * blockDim.x + threadIdx.x) >> 5;
    int lane = threadIdx.x & 31;
    if (t >= E_INTRA) return;
    int m = (t >= g_base[1]) + (t >= g_base[2]);
    int s = g_bsrc[t], d = g_bdst[t];
    float4 pv = *(const float4*)(g_ebuf + (size_t)t * 4);
    float4 dn = *(const float4*)(g_den + d * 16 + m * 4);
    float a0 = pv.x / fmaxf(dn.x, 1e-16f) * 0.25f;
    float a1 = pv.y / fmaxf(dn.y, 1e-16f) * 0.25f;
    float a2 = pv.z / fmaxf(dn.z, 1e-16f) * 0.25f;
    float a3 = pv.w / fmaxf(dn.w, 1e-16f) * 0.25f;
    const float* hr = g_h + ((size_t)m * N_NODES + s) * 256;
    float acc0 = a0 * hr[lane]       + a1 * hr[64 + lane]
               + a2 * hr[128 + lane] + a3 * hr[192 + lane];
    float acc1 = a0 * hr[32 + lane]  + a1 * hr[96 + lane]
               + a2 * hr[160 + lane] + a3 * hr[224 + lane];
    atomicAdd(out + (size_t)d * 64 + lane, acc0);
    atomicAdd(out + (size_t)d * 64 + 32 + lane, acc1);
}
__global__ __launch_bounds__(256) void agg_inter_k(const int* __restrict__ src,
                                                   const int* __restrict__ dst,
                                                   float* __restrict__ out) {
    int t = (blockIdx.x * blockDim.x + threadIdx.x) >> 5;
    int lane = threadIdx.x & 31;
    if (t >= E_INTER) return;
    int s = __ldg(src + t), d = __ldg(dst + t);
    float4 pv = *(const float4*)(g_ebuf + (size_t)(E_INTRA + t) * 4);
    float4 dn = *(const float4*)(g_den + d * 16 + 12);
    float a0 = pv.x / fmaxf(dn.x, 1e-16f) * 0.25f;
    float a1 = pv.y / fmaxf(dn.y, 1e-16f) * 0.25f;
    float a2 = pv.z / fmaxf(dn.z, 1e-16f) * 0.25f;
    float a3 = pv.w / fmaxf(dn.w, 1e-16f) * 0.25f;
    const float* hr = g_h + ((size_t)3 * N_NODES + s) * 256;
    float acc0 = a0 * hr[lane]       + a1 * hr[64 + lane]
               + a2 * hr[128 + lane] + a3 * hr[192 + lane];
    float acc1 = a0 * hr[32 + lane]  + a1 * hr[96 + lane]
               + a2 * hr[160 + lane] + a3 * hr[224 + lane];
    atomicAdd(out + (size_t)d * 64 + lane, acc0);
    atomicAdd(out + (size_t)d * 64 + 32 + lane, acc1);
}

// ---------------- launch ----------------
extern "C" void kernel_launch(void* const* d_in, const int* in_sizes, int n_in,
                              void* d_out, int out_size) {
    const float* x        = (const float*)d_in[0];
    const int*   modality = (const int*)d_in[1];
    const int*   isrc     = (const int*)d_in[2];
    const int*   idst     = (const int*)d_in[3];
    const int*   wsrc     = (const int*)d_in[4];
    const int*   wdst     = (const int*)d_in[5];
    const float* W_intra  = (const float*)d_in[6];
    const float* as_i     = (const float*)d_in[7];
    const float* ad_i     = (const float*)d_in[8];
    const float* b_i      = (const float*)d_in[9];
    const float* W_inter  = (const float*)d_in[10];
    const float* as_w     = (const float*)d_in[11];
    const float* ad_w     = (const float*)d_in[12];
    const float* b_w      = (const float*)d_in[13];
    float* out = (float*)d_out;

    const int GEMM_SMEM = (128 * XS_PITCH + 64 * 128) * 4;
    cudaFuncSetAttribute(gemm2_k, cudaFuncAttributeMaxDynamicSharedMemorySize, GEMM_SMEM);

    fold_k<<<8, 256>>>(W_intra, as_i, ad_i, W_inter, as_w, ad_w);
    asd_k<<<(N_NODES + 255) / 256, 256>>>(x);
    gemm2_k<<<dim3((N_NODES + 127) / 128, 2, 4), 256, GEMM_SMEM>>>(x, W_intra, W_inter);

    zero_k<<<(N_NODES * 16 + 255) / 256, 256>>>();
    init_out_k<<<(N_NODES * 64 + 255) / 256, 256>>>(out, b_i, b_w);

    count_k<<<(E_INTRA + 255) / 256, 256>>>(modality);
    base_k<<<1, 1>>>();
    scat_k<<<(E_INTRA + 255) / 256, 256>>>(isrc, idst, modality);

    fused_intra_k<<<(E_INTRA + 255) / 256, 256>>>();
    fused_inter_k<<<(E_INTER + 255) / 256, 256>>>(wsrc, wdst);

    agg_intra_k<<<(E_INTRA * 32 + 255) / 256, 256>>>(out);
    agg_inter_k<<<(E_INTER * 32 + 255) / 256, 256>>>(wsrc, wdst, out);
}

// round 3
// speedup vs baseline: 1.7150x; 1.2617x over previous
#include <cuda_runtime.h>
#include <cuda_fp16.h>

#define N_NODES 100000
#define E_INTRA 1000000
#define E_INTER 500000
#define E_TOT   (E_INTRA + E_INTER)
#define NSEG    400000            // 4 passes * 100K dst nodes
#define NB_SCAN 391               // ceil(400000/1024)
#define SHIFT   10.0f

// ---------------- scratch ----------------
__device__ __half  g_h[(size_t)4 * N_NODES * 256];  // [pass][n][head*64+c] fp16, 205MB
__device__ float   g_as[N_NODES * 16];              // [n][pass][head]
__device__ float   g_ad[N_NODES * 16];
__device__ float   g_fold[64 * 32];
__device__ int     g_cnt[NSEG];                     // per-segment counts
__device__ int     g_off[NSEG];                     // exclusive offsets
__device__ int     g_cur[NSEG];                     // scatter cursors
__device__ int     g_bsum[NB_SCAN];                 // scan block sums
__device__ int     g_esrc[E_TOT];                   // src per CSR slot

// ---------------- f32x2 packed math helpers ----------------
__device__ __forceinline__ unsigned long long pk2(float x) {
    unsigned long long r;
    asm("mov.b64 %0, {%1, %1};" : "=l"(r) : "f"(x));
    return r;
}
__device__ __forceinline__ void fma2(unsigned long long& acc, unsigned long long a,
                                     unsigned long long b) {
    asm("fma.rn.f32x2 %0, %1, %2, %0;" : "+l"(acc) : "l"(a), "l"(b));
}
__device__ __forceinline__ float2 upk(unsigned long long v) {
    float2 f;
    asm("mov.b64 {%0, %1}, %2;" : "=f"(f.x), "=f"(f.y) : "l"(v));
    return f;
}

// ---------------- small setup kernels ----------------
__global__ void zero_k() {
    int i = blockIdx.x * blockDim.x + threadIdx.x;
    if (i < NSEG) g_cnt[i] = 0;
}

__global__ void fold_k(const float* __restrict__ Wi, const float* __restrict__ asi,
                       const float* __restrict__ adi, const float* __restrict__ Ww,
                       const float* __restrict__ asw, const float* __restrict__ adw) {
    int idx = blockIdx.x * blockDim.x + threadIdx.x;
    if (idx >= 64 * 32) return;
    int f = idx >> 5, o = idx & 31;
    int sd = o >> 4, p = (o >> 2) & 3, h = o & 3;
    const float* W = (p < 3) ? (Wi + p * 64 * 256) : Ww;
    const float* att;
    if (p < 3) att = (sd ? adi : asi) + p * 4 * 64 + h * 64;
    else       att = (sd ? adw : asw) + h * 64;
    const float* wr = W + f * 256 + h * 64;
    float s = 0.f;
    #pragma unroll 16
    for (int c = 0; c < 64; c++) s += wr[c] * att[c];
    g_fold[f * 32 + o] = s;
}

__global__ __launch_bounds__(256) void asd_k(const float* __restrict__ x) {
    __shared__ float sf[64 * 32];
    for (int i = threadIdx.x; i < 2048; i += 256) sf[i] = g_fold[i];
    __syncthreads();
    int n = blockIdx.x * blockDim.x + threadIdx.x;
    if (n >= N_NODES) return;
    float acc[32];
    #pragma unroll
    for (int o = 0; o < 32; o++) acc[o] = 0.f;
    const float4* xr = (const float4*)(x + (size_t)n * 64);
    #pragma unroll
    for (int f4 = 0; f4 < 16; f4++) {
        float4 xv = __ldg(xr + f4);
        int f = f4 * 4;
        #pragma unroll
        for (int o = 0; o < 32; o++) {
            acc[o] += xv.x * sf[(f + 0) * 32 + o] + xv.y * sf[(f + 1) * 32 + o]
                    + xv.z * sf[(f + 2) * 32 + o] + xv.w * sf[(f + 3) * 32 + o];
        }
    }
    float4* as4 = (float4*)(g_as + n * 16);
    float4* ad4 = (float4*)(g_ad + n * 16);
    #pragma unroll
    for (int q = 0; q < 4; q++) {
        as4[q] = make_float4(acc[q * 4 + 0], acc[q * 4 + 1], acc[q * 4 + 2], acc[q * 4 + 3]);
        ad4[q] = make_float4(acc[16 + q * 4 + 0], acc[16 + q * 4 + 1], acc[16 + q * 4 + 2], acc[16 + q * 4 + 3]);
    }
}

// ---------------- h = x @ W_p : 128x128 tile, K=64, f32x2 FMA, fp16 out ----------------
#define XS_PITCH 68
__global__ __launch_bounds__(256, 2) void gemm2_k(const float* __restrict__ x,
                                                  const float* __restrict__ Wi,
                                                  const float* __restrict__ Ww) {
    extern __shared__ float smem[];
    float* xs = smem;                  // [128][XS_PITCH]
    float* ws = smem + 128 * XS_PITCH; // [64][128]
    int p = blockIdx.z;
    const float* W = (p < 3) ? (Wi + p * 64 * 256) : Ww;
    int row0 = blockIdx.x * 128;
    int col0 = blockIdx.y * 128;
    int tid = threadIdx.x;

    #pragma unroll
    for (int i = 0; i < 8; i++) {
        int idx = tid + i * 256;
        int r = idx >> 4, kq = idx & 15;
        float4 v = make_float4(0.f, 0.f, 0.f, 0.f);
        int row = row0 + r;
        if (row < N_NODES) v = *(const float4*)(x + (size_t)row * 64 + kq * 4);
        *(float4*)(xs + r * XS_PITCH + kq * 4) = v;
    }
    #pragma unroll
    for (int i = 0; i < 8; i++) {
        int idx = tid + i * 256;
        int k = idx >> 5, cq = idx & 31;
        *(float4*)(ws + k * 128 + cq * 4) = *(const float4*)(W + k * 256 + col0 + cq * 4);
    }
    __syncthreads();

    int tx = tid & 15, ty = tid >> 4;
    unsigned long long acc[8][4];
    #pragma unroll
    for (int i = 0; i < 8; i++)
        #pragma unroll
        for (int j = 0; j < 4; j++) acc[i][j] = 0ull;

    const float* xbase = xs + ty * 8 * XS_PITCH;
    #pragma unroll 8
    for (int k = 0; k < 64; k++) {
        ulonglong2 B0 = *(const ulonglong2*)(ws + k * 128 + tx * 8);
        ulonglong2 B1 = *(const ulonglong2*)(ws + k * 128 + tx * 8 + 4);
        #pragma unroll
        for (int i = 0; i < 8; i++) {
            unsigned long long aa = pk2(xbase[i * XS_PITCH + k]);
            fma2(acc[i][0], aa, B0.x);
            fma2(acc[i][1], aa, B0.y);
            fma2(acc[i][2], aa, B1.x);
            fma2(acc[i][3], aa, B1.y);
        }
    }

    #pragma unroll
    for (int i = 0; i < 8; i++) {
        int row = row0 + ty * 8 + i;
        if (row < N_NODES) {
            __half* op = g_h + ((size_t)p * N_NODES + row) * 256 + col0 + tx * 8;
            float2 f0 = upk(acc[i][0]), f1 = upk(acc[i][1]);
            float2 f2 = upk(acc[i][2]), f3 = upk(acc[i][3]);
            __half2 h0 = __float22half2_rn(f0);
            __half2 h1 = __float22half2_rn(f1);
            __half2 h2 = __float22half2_rn(f2);
            __half2 h3 = __float22half2_rn(f3);
            uint4 pk;
            pk.x = *(unsigned*)&h0; pk.y = *(unsigned*)&h1;
            pk.z = *(unsigned*)&h2; pk.w = *(unsigned*)&h3;
            *(uint4*)op = pk;
        }
    }
}

__global__ void init_out_k(float* __restrict__ out, const float* __restrict__ bi,
                           const float* __restrict__ bw) {
    int i = blockIdx.x * blockDim.x + threadIdx.x;
    if (i < N_NODES * 64) {
        int c = i & 63;
        out[i] = bi[c] + bi[64 + c] + bi[128 + c] + bw[c];
    }
}

// ---------------- CSR build: histogram -> scan -> scatter ----------------
__global__ void hist_k(const int* __restrict__ mod, const int* __restrict__ idst,
                       const int* __restrict__ wdst) {
    int e = blockIdx.x * blockDim.x + threadIdx.x;
    if (e >= E_TOT) return;
    int key;
    if (e < E_INTRA) key = __ldg(mod + e) * N_NODES + __ldg(idst + e);
    else             key = 3 * N_NODES + __ldg(wdst + e - E_INTRA);
    atomicAdd(&g_cnt[key], 1);
}

__global__ __launch_bounds__(256) void scan1_k() {
    __shared__ int sw[8];
    int b = blockIdx.x, t = threadIdx.x;
    int lane = t & 31, wid = t >> 5;
    int base = b * 1024 + t * 4;
    int v0 = (base + 0 < NSEG) ? g_cnt[base + 0] : 0;
    int v1 = (base + 1 < NSEG) ? g_cnt[base + 1] : 0;
    int v2 = (base + 2 < NSEG) ? g_cnt[base + 2] : 0;
    int v3 = (base + 3 < NSEG) ? g_cnt[base + 3] : 0;
    int tsum = v0 + v1 + v2 + v3;
    int incl = tsum;
    #pragma unroll
    for (int o = 1; o < 32; o <<= 1) {
        int n = __shfl_up_sync(0xffffffffu, incl, o);
        if (lane >= o) incl += n;
    }
    if (lane == 31) sw[wid] = incl;
    __syncthreads();
    int wbase = 0;
    for (int i = 0; i < 8; i++) if (i < wid) wbase += sw[i];
    int texcl = wbase + incl - tsum;
    if (base + 0 < NSEG) g_off[base + 0] = texcl;
    if (base + 1 < NSEG) g_off[base + 1] = texcl + v0;
    if (base + 2 < NSEG) g_off[base + 2] = texcl + v0 + v1;
    if (base + 3 < NSEG) g_off[base + 3] = texcl + v0 + v1 + v2;
    if (t == 255) g_bsum[b] = texcl + tsum;
}

__global__ __launch_bounds__(512) void scan2_k() {
    __shared__ int sw[16];
    int t = threadIdx.x, lane = t & 31, wid = t >> 5;
    int v = (t < NB_SCAN) ? g_bsum[t] : 0;
    int incl = v;
    #pragma unroll
    for (int o = 1; o < 32; o <<= 1) {
        int n = __shfl_up_sync(0xffffffffu, incl, o);
        if (lane >= o) incl += n;
    }
    if (lane == 31) sw[wid] = incl;
    __syncthreads();
    int wbase = 0;
    for (int i = 0; i < 16; i++) if (i < wid) wbase += sw[i];
    if (t < NB_SCAN) g_bsum[t] = wbase + incl - v;   // exclusive
}

__global__ void scan3_k() {
    int i = blockIdx.x * blockDim.x + threadIdx.x;
    if (i >= NSEG) return;
    int o = g_off[i] + g_bsum[i >> 10];
    g_off[i] = o;
    g_cur[i] = o;
}

__global__ void scat_k(const int* __restrict__ mod,
                       const int* __restrict__ isrc, const int* __restrict__ idst,
                       const int* __restrict__ wsrc, const int* __restrict__ wdst) {
    int e = blockIdx.x * blockDim.x + threadIdx.x;
    if (e >= E_TOT) return;
    int key, s;
    if (e < E_INTRA) {
        key = __ldg(mod + e) * N_NODES + __ldg(idst + e);
        s = __ldg(isrc + e);
    } else {
        key = 3 * N_NODES + __ldg(wdst + e - E_INTRA);
        s = __ldg(wsrc + e - E_INTRA);
    }
    int pos = atomicAdd(&g_cur[key], 1);
    g_esrc[pos] = s;
}

// ---------------- fused softmax + aggregate: one warp per segment ----------------
__device__ __forceinline__ float4 edge_p(int s, float4 ad, int aoff) {
    float4 as = *(const float4*)(g_as + s * 16 + aoff);
    float v0 = as.x + ad.x; v0 = v0 > 0.f ? v0 : 0.2f * v0;
    float v1 = as.y + ad.y; v1 = v1 > 0.f ? v1 : 0.2f * v1;
    float v2 = as.z + ad.z; v2 = v2 > 0.f ? v2 : 0.2f * v2;
    float v3 = as.w + ad.w; v3 = v3 > 0.f ? v3 : 0.2f * v3;
    return make_float4(__expf(v0 - SHIFT), __expf(v1 - SHIFT),
                       __expf(v2 - SHIFT), __expf(v3 - SHIFT));
}

__global__ __launch_bounds__(256) void agg_k(float* __restrict__ out) {
    __shared__ float4 pbuf[8][64];
    int seg = (blockIdx.x * blockDim.x + threadIdx.x) >> 5;
    int lane = threadIdx.x & 31;
    int wid = (threadIdx.x >> 5);
    if (seg >= NSEG) return;
    int off0 = g_off[seg];
    int off1 = (seg + 1 < NSEG) ? g_off[seg + 1] : E_TOT;
    int deg = off1 - off0;
    if (deg == 0) return;
    int pass = seg / N_NODES;
    int dst = seg - pass * N_NODES;
    int aoff = pass * 4;
    float4 ad = *(const float4*)(g_ad + dst * 16 + aoff);

    // phase A: denominators (+ stash p for first 64 edges)
    float d0 = 0.f, d1 = 0.f, d2 = 0.f, d3 = 0.f;
    for (int j = lane; j < deg; j += 32) {
        int s = g_esrc[off0 + j];
        float4 p = edge_p(s, ad, aoff);
        if (j < 64) pbuf[wid][j] = p;
        d0 += p.x; d1 += p.y; d2 += p.z; d3 += p.w;
    }
    #pragma unroll
    for (int o = 16; o > 0; o >>= 1) {
        d0 += __shfl_xor_sync(0xffffffffu, d0, o);
        d1 += __shfl_xor_sync(0xffffffffu, d1, o);
        d2 += __shfl_xor_sync(0xffffffffu, d2, o);
        d3 += __shfl_xor_sync(0xffffffffu, d3, o);
    }
    float i0 = 0.25f / fmaxf(d0, 1e-16f);
    float i1 = 0.25f / fmaxf(d1, 1e-16f);
    float i2 = 0.25f / fmaxf(d2, 1e-16f);
    float i3 = 0.25f / fmaxf(d3, 1e-16f);

    // phase B: gather h rows; lane covers cols 2*lane, 2*lane+1
    float acc0 = 0.f, acc1 = 0.f;
    for (int j = 0; j < deg; j++) {
        int s = g_esrc[off0 + j];       // broadcast load
        float4 p;
        if (j < 64) p = pbuf[wid][j];
        else        p = edge_p(s, ad, aoff);
        float a0 = p.x * i0, a1 = p.y * i1, a2 = p.z * i2, a3 = p.w * i3;
        const __half2* hr = (const __half2*)(g_h + ((size_t)pass * N_NODES + s) * 256);
        float2 x0 = __half22float2(hr[lane]);
        float2 x1 = __half22float2(hr[32 + lane]);
        float2 x2 = __half22float2(hr[64 + lane]);
        float2 x3 = __half22float2(hr[96 + lane]);
        acc0 += a0 * x0.x + a1 * x1.x + a2 * x2.x + a3 * x3.x;
        acc1 += a0 * x0.y + a1 * x1.y + a2 * x2.y + a3 * x3.y;
    }
    atomicAdd(out + (size_t)dst * 64 + 2 * lane, acc0);
    atomicAdd(out + (size_t)dst * 64 + 2 * lane + 1, acc1);
}

// ---------------- launch ----------------
extern "C" void kernel_launch(void* const* d_in, const int* in_sizes, int n_in,
                              void* d_out, int out_size) {
    const float* x        = (const float*)d_in[0];
    const int*   modality = (const int*)d_in[1];
    const int*   isrc     = (const int*)d_in[2];
    const int*   idst     = (const int*)d_in[3];
    const int*   wsrc     = (const int*)d_in[4];
    const int*   wdst     = (const int*)d_in[5];
    const float* W_intra  = (const float*)d_in[6];
    const float* as_i     = (const float*)d_in[7];
    const float* ad_i     = (const float*)d_in[8];
    const float* b_i      = (const float*)d_in[9];
    const float* W_inter  = (const float*)d_in[10];
    const float* as_w     = (const float*)d_in[11];
    const float* ad_w     = (const float*)d_in[12];
    const float* b_w      = (const float*)d_in[13];
    float* out = (float*)d_out;

    const int GEMM_SMEM = (128 * XS_PITCH + 64 * 128) * 4;
    cudaFuncSetAttribute(gemm2_k, cudaFuncAttributeMaxDynamicSharedMemorySize, GEMM_SMEM);

    zero_k<<<(NSEG + 255) / 256, 256>>>();                       // 1
    fold_k<<<8, 256>>>(W_intra, as_i, ad_i, W_inter, as_w, ad_w); // 2
    asd_k<<<(N_NODES + 255) / 256, 256>>>(x);                    // 3
    gemm2_k<<<dim3((N_NODES + 127) / 128, 2, 4), 256, GEMM_SMEM>>>(x, W_intra, W_inter); // 4 (profiled)
    init_out_k<<<(N_NODES * 64 + 255) / 256, 256>>>(out, b_i, b_w);
    hist_k<<<(E_TOT + 255) / 256, 256>>>(modality, idst, wdst);
    scan1_k<<<NB_SCAN, 256>>>();
    scan2_k<<<1, 512>>>();
    scan3_k<<<(NSEG + 255) / 256, 256>>>();
    scat_k<<<(E_TOT + 255) / 256, 256>>>(modality, isrc, idst, wsrc, wdst);
    agg_k<<<(NSEG * 32 + 255) / 256, 256>>>(out);
}